// round 1
// baseline (speedup 1.0000x reference)
#include <cuda_runtime.h>

// ---------------- problem constants ----------------
constexpr int T_  = 16;
constexpr int N_  = 50000;
constexpr int F_  = 128;
constexpr int B_  = 1024;
constexpr int S0_ = 10;
constexpr int S1_ = 5;
constexpr int H0_ = 128;
constexpr int H1_ = 64;
constexpr int C_  = 10;
constexpr int G_  = 8;
constexpr int K_  = 5;

constexpr int ROWS0 = B_ + B_ * S0_;   // 11264 rows per time step for layer 0
constexpr int M0    = T_ * ROWS0;      // 180224
constexpr int M1    = T_ * B_;         // 16384
constexpr int KD    = 256;             // concatenated K dim: [self | neigh]

// ---------------- device scratch (static, no allocs) ----------------
__device__ float g_A0[(size_t)M0 * KD];     // gathered [self|neigh] features  (~184.5 MB)
__device__ float g_spk0[(size_t)M0 * H0_];  // layer-0 spikes                  (~92 MB)
__device__ float g_A1[(size_t)M1 * KD];     // [spk_self | mean(spk_nb)]       (~16.8 MB)
__device__ float g_spk1[(size_t)M1 * H1_];  // layer-1 spikes                  (~4.2 MB)
__device__ float g_W0[KD * H0_];            // [W_self0 ; W_neigh0]
__device__ float g_W1[KD * H1_];            // [W_self1 ; W_neigh1]
__device__ float g_M[T_ * H1_ * C_];        // folded tail: delay+conv+pointwise/T

// ---------------- prep: weight concat + tail-fold table ----------------
__global__ void prep_kernel(const float* __restrict__ dl, const float* __restrict__ dw,
                            const float* __restrict__ pw,
                            const float* __restrict__ Ws0, const float* __restrict__ Wn0,
                            const float* __restrict__ Ws1, const float* __restrict__ Wn1) {
    int tid = threadIdx.x;  // 256 threads
    for (int i = tid; i < KD * H0_; i += 256) {
        int k = i / H0_, n = i % H0_;
        g_W0[i] = (k < F_) ? Ws0[k * H0_ + n] : Wn0[(k - F_) * H0_ + n];
    }
    for (int i = tid; i < KD * H1_; i += 256) {
        int k = i / H1_, n = i % H1_;
        g_W1[i] = (k < H0_) ? Ws1[k * H1_ + n] : Wn1[(k - H0_) * H1_ + n];
    }
    if (tid < H1_) {
        int h = tid, g = h / (H1_ / G_);
        // softmax over 3 delay logits for this channel's group
        float l0 = dl[g * 3 + 0], l1 = dl[g * 3 + 1], l2 = dl[g * 3 + 2];
        float mx = fmaxf(l0, fmaxf(l1, l2));
        float e0 = expf(l0 - mx), e1 = expf(l1 - mx), e2 = expf(l2 - mx);
        float inv = 1.0f / (e0 + e1 + e2);
        float w[3] = {e0 * inv, e1 * inv, e2 * inv};
        // cw[u] = sum over valid conv taps when summing y over t (SAME pad=2, cross-corr)
        float cw[T_];
        for (int u = 0; u < T_; u++) {
            float a = 0.f;
            for (int k = 0; k < K_; k++) {
                int t = u - k + 2;
                if (t >= 0 && t < T_) a += dw[h * K_ + k];
            }
            cw[u] = a;
        }
        const int D[3] = {1, 3, 5};
        for (int s = 0; s < T_; s++) {
            float coef = 0.f;
            for (int i = 0; i < 3; i++) {
                int u = s + D[i];
                if (u < T_) coef += w[i] * cw[u];
            }
            for (int c = 0; c < C_; c++)
                g_M[(s * H1_ + h) * C_ + c] = coef * pw[h * C_ + c] * (1.0f / T_);
        }
    }
}

// ---------------- gather: build A0 = [self | neigh_mean] ----------------
__global__ void gather_kernel(const float* __restrict__ x, const int* __restrict__ nodes,
                              const int* __restrict__ nbr1, const int* __restrict__ nbr2) {
    int gid = blockIdx.x;          // t*ROWS0 + r
    int t = gid / ROWS0, r = gid % ROWS0;
    int f = threadIdx.x;           // 128 threads, one per feature
    const float* xt = x + (size_t)t * N_ * F_;
    float sv, nv = 0.f;
    if (r < B_) {
        sv = xt[(size_t)nodes[r] * F_ + f];
        const int* nb = nbr1 + ((size_t)t * B_ + r) * S0_;
#pragma unroll
        for (int s = 0; s < S0_; s++) nv += xt[(size_t)nb[s] * F_ + f];
        nv *= (1.0f / S0_);
    } else {
        int j = r - B_;
        sv = xt[(size_t)nbr1[(size_t)t * B_ * S0_ + j] * F_ + f];
        const int* nb = nbr2 + ((size_t)t * B_ * S0_ + j) * S1_;
#pragma unroll
        for (int s = 0; s < S1_; s++) nv += xt[(size_t)nb[s] * F_ + f];
        nv *= (1.0f / S1_);
    }
    float* dst = g_A0 + (size_t)gid * KD;
    dst[f] = sv;
    dst[F_ + f] = nv;
}

// ---------------- tiled fp32 GEMM + bias + spike threshold ----------------
template <int BN, int TN>
__device__ __forceinline__ void gemm_spike_body(const float* __restrict__ A,
                                                const float* __restrict__ W,
                                                const float* __restrict__ bias,
                                                float* __restrict__ out) {
    constexpr int BM = 128, BK = 32, TM = 8;
    __shared__ float As[BK][BM + 4];   // transposed A tile, padded vs bank conflicts
    __shared__ float Bs[BK][BN];
    int tid = threadIdx.x;             // 256
    int tx = tid & 15;                 // n direction (16)
    int ty = tid >> 4;                 // m direction (16)
    size_t m0 = (size_t)blockIdx.x * BM;

    float acc[TM][TN];
#pragma unroll
    for (int i = 0; i < TM; i++)
#pragma unroll
        for (int j = 0; j < TN; j++) acc[i][j] = 0.f;

    int a_r = tid >> 3;                // 32 rows per pass
    int a_c = (tid & 7) << 2;          // 8 float4 per 32-wide row
    constexpr int BTPR = BN / 4;       // float4 per B row
    constexpr int BRPP = 256 / BTPR;   // B rows per pass
    int b_r = tid / BTPR;
    int b_c = (tid % BTPR) * 4;

    for (int k0 = 0; k0 < KD; k0 += BK) {
#pragma unroll
        for (int p = 0; p < 4; p++) {
            int row = a_r + p * 32;
            float4 v = *(const float4*)(A + (m0 + row) * KD + k0 + a_c);
            As[a_c + 0][row] = v.x; As[a_c + 1][row] = v.y;
            As[a_c + 2][row] = v.z; As[a_c + 3][row] = v.w;
        }
#pragma unroll
        for (int p = 0; p < BK / BRPP; p++) {
            int row = b_r + p * BRPP;
            *(float4*)(&Bs[row][b_c]) = *(const float4*)(W + (size_t)(k0 + row) * BN + b_c);
        }
        __syncthreads();
#pragma unroll
        for (int kk = 0; kk < BK; kk++) {
            float a[TM], b[TN];
#pragma unroll
            for (int i = 0; i < TM; i++) a[i] = As[kk][ty * TM + i];
#pragma unroll
            for (int j = 0; j < TN; j++) b[j] = Bs[kk][tx * TN + j];
#pragma unroll
            for (int i = 0; i < TM; i++)
#pragma unroll
                for (int j = 0; j < TN; j++) acc[i][j] = fmaf(a[i], b[j], acc[i][j]);
        }
        __syncthreads();
    }
    // epilogue: + bias, spike threshold (TAU=1 => v_c == a), write 0/1
#pragma unroll
    for (int i = 0; i < TM; i++) {
        size_t m = m0 + ty * TM + i;
#pragma unroll
        for (int j = 0; j < TN; j++) {
            float v = acc[i][j] + bias[tx * TN + j];
            acc[i][j] = (v >= 1.0f) ? 1.0f : 0.0f;
        }
#pragma unroll
        for (int j = 0; j < TN; j += 4) {
            float4 v4 = make_float4(acc[i][j], acc[i][j + 1], acc[i][j + 2], acc[i][j + 3]);
            *(float4*)(out + m * BN + tx * TN + j) = v4;
        }
    }
}

__global__ __launch_bounds__(256) void gemm0_kernel(const float* __restrict__ bias) {
    gemm_spike_body<128, 8>(g_A0, g_W0, bias, g_spk0);
}
__global__ __launch_bounds__(256) void gemm1_kernel(const float* __restrict__ bias) {
    gemm_spike_body<64, 4>(g_A1, g_W1, bias, g_spk1);
}

// ---------------- A1 = [spk_self | mean_{S0}(spk_nb)] ----------------
__global__ void buildA1_kernel() {
    int gid = blockIdx.x;              // t*B + b
    int t = gid / B_, b = gid % B_;
    int h = threadIdx.x;               // 128
    size_t base = (size_t)t * ROWS0;
    float s_self = g_spk0[(base + b) * H0_ + h];
    float acc = 0.f;
#pragma unroll
    for (int s = 0; s < S0_; s++)
        acc += g_spk0[(base + B_ + (size_t)b * S0_ + s) * H0_ + h];
    float* dst = g_A1 + (size_t)gid * KD;
    dst[h] = s_self;
    dst[H0_ + h] = acc * (1.0f / S0_);
}

// ---------------- final: out[b,c] = tsr_b[c] + sum_{s,h} spk1*M ----------------
__global__ void final_kernel(const float* __restrict__ tb, float* __restrict__ out) {
    __shared__ float red[H1_][C_];
    int b = blockIdx.x, h = threadIdx.x;   // 64 threads
    float acc[C_];
#pragma unroll
    for (int c = 0; c < C_; c++) acc[c] = 0.f;
    for (int t = 0; t < T_; t++) {
        float s = g_spk1[((size_t)t * B_ + b) * H1_ + h];
        const float* m = g_M + (t * H1_ + h) * C_;
#pragma unroll
        for (int c = 0; c < C_; c++) acc[c] = fmaf(s, m[c], acc[c]);
    }
#pragma unroll
    for (int c = 0; c < C_; c++) red[h][c] = acc[c];
    __syncthreads();
    if (h < C_) {
        float s = tb[h];
        for (int r = 0; r < H1_; r++) s += red[r][h];
        out[b * C_ + h] = s;
    }
}

// ---------------- launch ----------------
extern "C" void kernel_launch(void* const* d_in, const int* in_sizes, int n_in,
                              void* d_out, int out_size) {
    const float* x    = (const float*)d_in[0];
    const int*   nodes= (const int*)d_in[1];
    const int*   nbr1 = (const int*)d_in[2];
    const int*   nbr2 = (const int*)d_in[3];
    const float* Ws0  = (const float*)d_in[4];
    const float* Wn0  = (const float*)d_in[5];
    const float* b0   = (const float*)d_in[6];
    const float* Ws1  = (const float*)d_in[7];
    const float* Wn1  = (const float*)d_in[8];
    const float* b1   = (const float*)d_in[9];
    const float* dl   = (const float*)d_in[10];
    const float* dw   = (const float*)d_in[11];
    const float* pw   = (const float*)d_in[12];
    const float* tb   = (const float*)d_in[13];
    float* out = (float*)d_out;

    prep_kernel<<<1, 256>>>(dl, dw, pw, Ws0, Wn0, Ws1, Wn1);
    gather_kernel<<<M0, 128>>>(x, nodes, nbr1, nbr2);
    gemm0_kernel<<<M0 / 128, 256>>>(b0);
    buildA1_kernel<<<M1, 128>>>();
    gemm1_kernel<<<M1 / 128, 256>>>(b1);
    final_kernel<<<B_, 64>>>(tb, out);
}

// round 4
// speedup vs baseline: 1.1662x; 1.1662x over previous
#include <cuda_runtime.h>
#include <cuda_bf16.h>
#include <cuda_fp16.h>
#include <cstdint>

// ---------------- problem constants ----------------
constexpr int T_  = 16;
constexpr int N_  = 50000;
constexpr int F_  = 128;
constexpr int B_  = 1024;
constexpr int S0_ = 10;
constexpr int S1_ = 5;
constexpr int H0_ = 128;
constexpr int H1_ = 64;
constexpr int C_  = 10;
constexpr int G_  = 8;
constexpr int K_  = 5;

constexpr int ROWS0 = B_ + B_ * S0_;   // 11264 rows per time step
constexpr int M0    = T_ * ROWS0;      // 180224
constexpr int M1    = T_ * B_;         // 16384
constexpr int KD    = 256;             // concat K dim [self | neigh]

constexpr float TAU_FIX = 1e-3f;       // borderline-detection band around threshold
constexpr uint32_t FIX_CAP = 1u << 20; // fixup list capacity

// ---------------- device scratch ----------------
__device__ __nv_bfloat16 g_spk0[(size_t)M0 * H0_];  // layer-0 spikes, bf16 0/1 (46 MB)
__device__ float g_A1[(size_t)M1 * KD];
__device__ float g_spk1[(size_t)M1 * H1_];
__device__ float g_W1[KD * H1_];
__device__ float g_M[T_ * H1_ * C_];
// pre-swizzled fp16 W0 images: [k-phase][hi/lo], each 128k x 128n fp16 = 32KB
__device__ __align__(16) char g_W0img[2][2][32768];
__device__ uint32_t g_fix[FIX_CAP];
__device__ uint32_t g_nfix;

// ================= helpers =================
__device__ __forceinline__ uint32_t smem_u32(const void* p) {
    uint32_t a;
    asm("{ .reg .u64 t; cvta.to.shared.u64 t, %1; cvt.u32.u64 %0, t; }" : "=r"(a) : "l"(p));
    return a;
}
__device__ __forceinline__ void ldsm_x4(uint32_t* r, uint32_t addr) {
    asm volatile("ldmatrix.sync.aligned.m8n8.x4.shared.b16 {%0,%1,%2,%3}, [%4];"
        : "=r"(r[0]), "=r"(r[1]), "=r"(r[2]), "=r"(r[3]) : "r"(addr));
}
__device__ __forceinline__ void ldsm_x4_t(uint32_t* r, uint32_t addr) {
    asm volatile("ldmatrix.sync.aligned.m8n8.x4.trans.shared.b16 {%0,%1,%2,%3}, [%4];"
        : "=r"(r[0]), "=r"(r[1]), "=r"(r[2]), "=r"(r[3]) : "r"(addr));
}
__device__ __forceinline__ void mma16816(float* d, const uint32_t* a, const uint32_t* b) {
    asm volatile("mma.sync.aligned.m16n8k16.row.col.f32.f16.f16.f32 "
        "{%0,%1,%2,%3}, {%4,%5,%6,%7}, {%8,%9}, {%0,%1,%2,%3};"
        : "+f"(d[0]), "+f"(d[1]), "+f"(d[2]), "+f"(d[3])
        : "r"(a[0]), "r"(a[1]), "r"(a[2]), "r"(a[3]), "r"(b[0]), "r"(b[1]));
}

// W image layout: row = k (0..127), 128 n fp16 => 256B/row, XOR-swizzled 16B chunks
__device__ __forceinline__ uint32_t wimg_off(int k, int n) {
    uint32_t chunk = (uint32_t)(n >> 3) ^ (uint32_t)(k & 7);
    return (uint32_t)(k * 256 + (chunk << 4) + (n & 7) * 2);
}
// A tile layout: row (0..127), 256 k fp16 => 512B/row, XOR-swizzled 16B chunks
__device__ __forceinline__ uint32_t atile_off(int row, int kk) {
    uint32_t chunk = (uint32_t)(kk >> 3) ^ (uint32_t)(row & 7);
    return (uint32_t)(row * 512 + (chunk << 4) + (kk & 7) * 2);
}

__device__ __forceinline__ void hsplit2(float a, float b, uint32_t& hi, uint32_t& lo) {
    __half ah = __float2half_rn(a);
    __half bh = __float2half_rn(b);
    __half al = __float2half_rn(a - __half2float(ah));
    __half bl = __float2half_rn(b - __half2float(bh));
    hi = (uint32_t)__half_as_ushort(ah) | ((uint32_t)__half_as_ushort(bh) << 16);
    lo = (uint32_t)__half_as_ushort(al) | ((uint32_t)__half_as_ushort(bl) << 16);
}

// ---------------- zero fixup counter ----------------
__global__ void zero_kernel() { g_nfix = 0; }

// ---------------- prep ----------------
__global__ void prep_kernel(const float* __restrict__ dl, const float* __restrict__ dw,
                            const float* __restrict__ pw,
                            const float* __restrict__ Ws0, const float* __restrict__ Wn0,
                            const float* __restrict__ Ws1, const float* __restrict__ Wn1) {
    int tid = threadIdx.x;  // 256
    for (int i = tid; i < 256 * 128; i += 256) {
        int k = i >> 7, n = i & 127;
        float w = (k < 128) ? Ws0[k * H0_ + n] : Wn0[(k - 128) * H0_ + n];
        __half wh = __float2half_rn(w);
        __half wl = __float2half_rn(w - __half2float(wh));
        int ph = k >> 7, kl = k & 127;
        uint32_t off = wimg_off(kl, n);
        *(__half*)(g_W0img[ph][0] + off) = wh;
        *(__half*)(g_W0img[ph][1] + off) = wl;
    }
    for (int i = tid; i < KD * H1_; i += 256) {
        int k = i / H1_, n = i % H1_;
        g_W1[i] = (k < H0_) ? Ws1[k * H1_ + n] : Wn1[(k - H0_) * H1_ + n];
    }
    if (tid < H1_) {
        int h = tid, g = h / (H1_ / G_);
        float l0 = dl[g * 3 + 0], l1 = dl[g * 3 + 1], l2 = dl[g * 3 + 2];
        float mx = fmaxf(l0, fmaxf(l1, l2));
        float e0 = expf(l0 - mx), e1 = expf(l1 - mx), e2 = expf(l2 - mx);
        float inv = 1.0f / (e0 + e1 + e2);
        float w[3] = {e0 * inv, e1 * inv, e2 * inv};
        float cw[T_];
        for (int u = 0; u < T_; u++) {
            float a = 0.f;
            for (int k = 0; k < K_; k++) {
                int t = u - k + 2;
                if (t >= 0 && t < T_) a += dw[h * K_ + k];
            }
            cw[u] = a;
        }
        const int D[3] = {1, 3, 5};
        for (int s = 0; s < T_; s++) {
            float coef = 0.f;
            for (int i2 = 0; i2 < 3; i2++) {
                int u = s + D[i2];
                if (u < T_) coef += w[i2] * cw[u];
            }
            for (int c = 0; c < C_; c++)
                g_M[(s * H1_ + h) * C_ + c] = coef * pw[h * C_ + c] * (1.0f / T_);
        }
    }
}

// ---------------- fused gather + HMMA fp16x2 GEMM0 + spike ----------------
constexpr int OFF_AH  = 0;        // 128x256 fp16 hi (64KB)
constexpr int OFF_AL  = 65536;    // 128x256 fp16 lo (64KB)
constexpr int OFF_WH  = 131072;   // 128x128 fp16 hi (32KB)
constexpr int OFF_WL  = 163840;   // 128x128 fp16 lo (32KB)
constexpr int OFF_SELF= 196608;   // 128 ints
constexpr int OFF_NBR = 197120;   // 128*10 ints
constexpr int OFF_BIAS= 202240;   // 128 floats
constexpr int SMEM_SZ = 202752;

template <int S>
__device__ __forceinline__ void do_gather(const float* __restrict__ xt,
                                          const int* __restrict__ s_self,
                                          const int* __restrict__ s_nbr,
                                          char* sm, int tid) {
    int hw = tid >> 4, j = tid & 15;
    const float invS = 1.0f / (float)S;
#pragma unroll 1
    for (int i = 0; i < 16; i++) {
        int task = hw * 16 + i;
        int row = task & 127;
        int half = task >> 7;
        int fo = half * 64 + j * 4;       // feature offset (floats), covers 0..127
        const float* sp = xt + (size_t)s_self[row] * F_ + fo;
        float4 sv = *(const float4*)sp;
        float4 nv = make_float4(0.f, 0.f, 0.f, 0.f);
#pragma unroll
        for (int s = 0; s < S; s++) {
            const float* np = xt + (size_t)s_nbr[row * S + s] * F_ + fo;
            float4 v = *(const float4*)np;
            nv.x += v.x; nv.y += v.y; nv.z += v.z; nv.w += v.w;
        }
        nv.x *= invS; nv.y *= invS; nv.z *= invS; nv.w *= invS;
        uint32_t h0, l0, h1, l1;
        hsplit2(sv.x, sv.y, h0, l0);
        hsplit2(sv.z, sv.w, h1, l1);
        *(uint2*)(sm + OFF_AH + atile_off(row, fo)) = make_uint2(h0, h1);
        *(uint2*)(sm + OFF_AL + atile_off(row, fo)) = make_uint2(l0, l1);
        hsplit2(nv.x, nv.y, h0, l0);
        hsplit2(nv.z, nv.w, h1, l1);
        *(uint2*)(sm + OFF_AH + atile_off(row, 128 + fo)) = make_uint2(h0, h1);
        *(uint2*)(sm + OFF_AL + atile_off(row, 128 + fo)) = make_uint2(l0, l1);
    }
}

__global__ __launch_bounds__(256, 1)
void gemm0_fused_kernel(const float* __restrict__ x, const int* __restrict__ nodes,
                        const int* __restrict__ nbr1, const int* __restrict__ nbr2,
                        const float* __restrict__ bias) {
    extern __shared__ __align__(1024) char sm[];
    uint32_t smb = smem_u32(sm);
    int tid = threadIdx.x;
    int wid = tid >> 5;
    int l   = tid & 31;

    size_t mblk = (size_t)blockIdx.x * 128;
    int t = (int)(mblk / ROWS0);
    int r0 = (int)(mblk % ROWS0);
    const float* xt = x + (size_t)t * N_ * F_;

    int* s_self = (int*)(sm + OFF_SELF);
    int* s_nbr  = (int*)(sm + OFF_NBR);
    float* s_bias = (float*)(sm + OFF_BIAS);

    // ---- index lists + bias + W phase-0 ----
    if (tid < 128) {
        s_bias[tid] = bias[tid];
        int r = r0 + tid;
        if (r < B_) {
            s_self[tid] = nodes[r];
            size_t base = ((size_t)t * B_ + r) * S0_;
#pragma unroll
            for (int s = 0; s < S0_; s++) s_nbr[tid * S0_ + s] = nbr1[base + s];
        } else {
            int j = r - B_;
            s_self[tid] = nbr1[(size_t)t * B_ * S0_ + j];
            size_t base = ((size_t)t * B_ * S0_ + j) * S1_;
#pragma unroll
            for (int s = 0; s < S1_; s++) s_nbr[tid * S1_ + s] = nbr2[base + s];
        }
    }
    {
        const uint4* srcH = (const uint4*)g_W0img[0][0];
        const uint4* srcL = (const uint4*)g_W0img[0][1];
        uint4* dstH = (uint4*)(sm + OFF_WH);
        uint4* dstL = (uint4*)(sm + OFF_WL);
        for (int i = tid; i < 2048; i += 256) { dstH[i] = srcH[i]; dstL[i] = srcL[i]; }
    }
    __syncthreads();

    // ---- gather A (all K=256) into fp16 hi/lo swizzled tiles ----
    if (r0 < B_) do_gather<S0_>(xt, s_self, s_nbr, sm, tid);
    else         do_gather<S1_>(xt, s_self, s_nbr, sm, tid);
    __syncthreads();

    // ---- warp tiling: 4 warps in M x 2 in N; warp does 32 rows x 64 cols ----
    int wm = wid & 3, wn = wid >> 2;
    int m0 = wm * 32;
    int nb0 = wn * 64;

    float acc[2][8][4];
#pragma unroll
    for (int a = 0; a < 2; a++)
#pragma unroll
        for (int b = 0; b < 8; b++)
#pragma unroll
            for (int c = 0; c < 4; c++) acc[a][b][c] = 0.f;

    // A ldmatrix lane constants
    uint32_t a_rowb[2]; int a_sw[2];
#pragma unroll
    for (int mt = 0; mt < 2; mt++) {
        int r = m0 + mt * 16 + (l & 15);
        a_rowb[mt] = (uint32_t)(r * 512);
        a_sw[mt] = r & 7;
    }
    int a_cs = l >> 4;
    // B ldmatrix lane constants
    int b_rowoff = (l & 7) + (l & 8);          // 0..15
    int b_sw = l & 7;
    int b_cs = l >> 4;
    uint32_t b_rowb = (uint32_t)(b_rowoff * 256);

#pragma unroll 1
    for (int ph = 0; ph < 2; ph++) {
        if (ph == 1) {
            __syncthreads();
            const uint4* srcH = (const uint4*)g_W0img[1][0];
            const uint4* srcL = (const uint4*)g_W0img[1][1];
            uint4* dstH = (uint4*)(sm + OFF_WH);
            uint4* dstL = (uint4*)(sm + OFF_WL);
            for (int i = tid; i < 2048; i += 256) { dstH[i] = srcH[i]; dstL[i] = srcL[i]; }
            __syncthreads();
        }
        int kc0 = ph * 16;
#pragma unroll
        for (int ks = 0; ks < 8; ks++) {
            int chunk0 = kc0 + ks * 2 + a_cs;
            uint32_t ah[2][4], al[2][4];
#pragma unroll
            for (int mt = 0; mt < 2; mt++) {
                uint32_t offc = (uint32_t)((chunk0 ^ a_sw[mt]) << 4);
                ldsm_x4(ah[mt], smb + OFF_AH + a_rowb[mt] + offc);
                ldsm_x4(al[mt], smb + OFF_AL + a_rowb[mt] + offc);
            }
            uint32_t wrow = b_rowb + (uint32_t)(ks * 4096);
#pragma unroll
            for (int n2 = 0; n2 < 4; n2++) {
                int chunkb = (nb0 >> 3) + n2 * 2 + b_cs;
                uint32_t offb = (uint32_t)((chunkb ^ b_sw) << 4);
                uint32_t bh[4], bl[4];
                ldsm_x4_t(bh, smb + OFF_WH + wrow + offb);
                ldsm_x4_t(bl, smb + OFF_WL + wrow + offb);
#pragma unroll
                for (int mt = 0; mt < 2; mt++) {
                    mma16816(acc[mt][n2 * 2 + 0], ah[mt], bh + 0);
                    mma16816(acc[mt][n2 * 2 + 1], ah[mt], bh + 2);
                    mma16816(acc[mt][n2 * 2 + 0], ah[mt], bl + 0);
                    mma16816(acc[mt][n2 * 2 + 1], ah[mt], bl + 2);
                    mma16816(acc[mt][n2 * 2 + 0], al[mt], bh + 0);
                    mma16816(acc[mt][n2 * 2 + 1], al[mt], bh + 2);
                }
            }
        }
    }

    // ---- epilogue: +bias, threshold, borderline detection, write bf16 0/1 ----
    int r_in = l >> 2;
    int c2 = (l & 3) * 2;
    const uint32_t ONE = 0x3F80u;   // bf16 1.0
#pragma unroll
    for (int mt = 0; mt < 2; mt++) {
        size_t grow0 = mblk + m0 + mt * 16 + r_in;
#pragma unroll
        for (int nt = 0; nt < 8; nt++) {
            int col = nb0 + nt * 8 + c2;
            float bb0 = s_bias[col], bb1 = s_bias[col + 1];
            float v00 = acc[mt][nt][0] + bb0;
            float v01 = acc[mt][nt][1] + bb1;
            float v10 = acc[mt][nt][2] + bb0;
            float v11 = acc[mt][nt][3] + bb1;
            uint32_t u0 = ((v00 >= 1.0f) ? ONE : 0u) | (((v01 >= 1.0f) ? ONE : 0u) << 16);
            uint32_t u1 = ((v10 >= 1.0f) ? ONE : 0u) | (((v11 >= 1.0f) ? ONE : 0u) << 16);
            *(uint32_t*)((char*)g_spk0 + (grow0 * H0_ + col) * 2) = u0;
            *(uint32_t*)((char*)g_spk0 + ((grow0 + 8) * H0_ + col) * 2) = u1;
            // borderline elements -> fixup list (rare)
            if (fabsf(v00 - 1.0f) < TAU_FIX) {
                uint32_t p = atomicAdd(&g_nfix, 1u);
                if (p < FIX_CAP) g_fix[p] = (uint32_t)(grow0 * H0_ + col);
            }
            if (fabsf(v01 - 1.0f) < TAU_FIX) {
                uint32_t p = atomicAdd(&g_nfix, 1u);
                if (p < FIX_CAP) g_fix[p] = (uint32_t)(grow0 * H0_ + col + 1);
            }
            if (fabsf(v10 - 1.0f) < TAU_FIX) {
                uint32_t p = atomicAdd(&g_nfix, 1u);
                if (p < FIX_CAP) g_fix[p] = (uint32_t)((grow0 + 8) * H0_ + col);
            }
            if (fabsf(v11 - 1.0f) < TAU_FIX) {
                uint32_t p = atomicAdd(&g_nfix, 1u);
                if (p < FIX_CAP) g_fix[p] = (uint32_t)((grow0 + 8) * H0_ + col + 1);
            }
        }
    }
}

// ---------------- fixup: recompute borderline a0 elements in fp32 ----------------
__global__ void fixup_kernel(const float* __restrict__ x, const int* __restrict__ nodes,
                             const int* __restrict__ nbr1, const int* __restrict__ nbr2,
                             const float* __restrict__ Ws0, const float* __restrict__ Wn0,
                             const float* __restrict__ b0) {
    uint32_t n = g_nfix;
    if (n > FIX_CAP) n = FIX_CAP;
    int lane = threadIdx.x & 31;
    int gw = (blockIdx.x * blockDim.x + threadIdx.x) >> 5;
    int nwarps = (gridDim.x * blockDim.x) >> 5;
    for (uint32_t i = gw; i < n; i += nwarps) {
        uint32_t e = g_fix[i];
        int col = (int)(e & 127);
        uint32_t m = e >> 7;
        int t = (int)(m / ROWS0);
        int r = (int)(m % ROWS0);
        const float* xt = x + (size_t)t * N_ * F_;
        int self; const int* nb; int S;
        if (r < B_) {
            self = nodes[r];
            nb = nbr1 + ((size_t)t * B_ + r) * S0_;
            S = S0_;
        } else {
            int j = r - B_;
            self = nbr1[(size_t)t * B_ * S0_ + j];
            nb = nbr2 + ((size_t)t * B_ * S0_ + j) * S1_;
            S = S1_;
        }
        float invS = 1.0f / (float)S;
        float acc = 0.f;
        for (int k = lane; k < F_; k += 32) {
            float sv = xt[(size_t)self * F_ + k];
            float nv = 0.f;
            for (int s = 0; s < S; s++) nv += xt[(size_t)nb[s] * F_ + k];
            nv *= invS;
            acc += sv * Ws0[k * H0_ + col] + nv * Wn0[k * H0_ + col];
        }
#pragma unroll
        for (int off = 16; off > 0; off >>= 1)
            acc += __shfl_xor_sync(0xFFFFFFFFu, acc, off);
        if (lane == 0) {
            float v = acc + b0[col];
            g_spk0[(size_t)m * H0_ + col] = (v >= 1.0f) ? __float2bfloat16(1.0f)
                                                        : __float2bfloat16(0.0f);
        }
    }
}

// ---------------- A1 = [spk_self | mean_{S0}(spk_nb)] ----------------
__global__ void buildA1_kernel() {
    int gid = blockIdx.x;
    int t = gid / B_, b = gid % B_;
    int h = threadIdx.x;
    size_t base = (size_t)t * ROWS0;
    float s_self = __bfloat162float(g_spk0[(base + b) * H0_ + h]);
    float acc = 0.f;
#pragma unroll
    for (int s = 0; s < S0_; s++)
        acc += __bfloat162float(g_spk0[(base + B_ + (size_t)b * S0_ + s) * H0_ + h]);
    float* dst = g_A1 + (size_t)gid * KD;
    dst[h] = s_self;
    dst[H0_ + h] = acc * (1.0f / S0_);
}

// ---------------- fp32 FFMA GEMM1 + spike ----------------
__global__ __launch_bounds__(256) void gemm1_kernel(const float* __restrict__ bias) {
    constexpr int BM = 128, BK = 32, TM = 8, BN = 64, TN = 4;
    __shared__ float As[BK][BM + 4];
    __shared__ float Bs[BK][BN];
    int tid = threadIdx.x;
    int tx = tid & 15, ty = tid >> 4;
    size_t mb = (size_t)blockIdx.x * BM;
    float acc[TM][TN];
#pragma unroll
    for (int i = 0; i < TM; i++)
#pragma unroll
        for (int j = 0; j < TN; j++) acc[i][j] = 0.f;
    int a_r = tid >> 3, a_c = (tid & 7) << 2;
    int b_r = tid / 16, b_c = (tid % 16) * 4;
    for (int k0 = 0; k0 < KD; k0 += BK) {
#pragma unroll
        for (int p = 0; p < 4; p++) {
            int row = a_r + p * 32;
            float4 v = *(const float4*)(g_A1 + (mb + row) * KD + k0 + a_c);
            As[a_c + 0][row] = v.x; As[a_c + 1][row] = v.y;
            As[a_c + 2][row] = v.z; As[a_c + 3][row] = v.w;
        }
#pragma unroll
        for (int p = 0; p < 2; p++) {
            int row = b_r + p * 16;
            *(float4*)(&Bs[row][b_c]) = *(const float4*)(g_W1 + (size_t)(k0 + row) * BN + b_c);
        }
        __syncthreads();
#pragma unroll
        for (int kk = 0; kk < BK; kk++) {
            float a[TM], b[TN];
#pragma unroll
            for (int i = 0; i < TM; i++) a[i] = As[kk][ty * TM + i];
#pragma unroll
            for (int j = 0; j < TN; j++) b[j] = Bs[kk][tx * TN + j];
#pragma unroll
            for (int i = 0; i < TM; i++)
#pragma unroll
                for (int j = 0; j < TN; j++) acc[i][j] = fmaf(a[i], b[j], acc[i][j]);
        }
        __syncthreads();
    }
#pragma unroll
    for (int i = 0; i < TM; i++) {
        size_t m = mb + ty * TM + i;
        float4 v;
        v.x = (acc[i][0] + bias[tx * TN + 0] >= 1.0f) ? 1.0f : 0.0f;
        v.y = (acc[i][1] + bias[tx * TN + 1] >= 1.0f) ? 1.0f : 0.0f;
        v.z = (acc[i][2] + bias[tx * TN + 2] >= 1.0f) ? 1.0f : 0.0f;
        v.w = (acc[i][3] + bias[tx * TN + 3] >= 1.0f) ? 1.0f : 0.0f;
        *(float4*)(g_spk1 + m * BN + tx * TN) = v;
    }
}

// ---------------- final contraction ----------------
__global__ void final_kernel(const float* __restrict__ tb, float* __restrict__ out) {
    __shared__ float red[H1_][C_];
    int b = blockIdx.x, h = threadIdx.x;
    float acc[C_];
#pragma unroll
    for (int c = 0; c < C_; c++) acc[c] = 0.f;
    for (int t = 0; t < T_; t++) {
        float s = g_spk1[((size_t)t * B_ + b) * H1_ + h];
        const float* m = g_M + (t * H1_ + h) * C_;
#pragma unroll
        for (int c = 0; c < C_; c++) acc[c] = fmaf(s, m[c], acc[c]);
    }
#pragma unroll
    for (int c = 0; c < C_; c++) red[h][c] = acc[c];
    __syncthreads();
    if (h < C_) {
        float s = tb[h];
        for (int r = 0; r < H1_; r++) s += red[r][h];
        out[b * C_ + h] = s;
    }
}

// ---------------- launch ----------------
extern "C" void kernel_launch(void* const* d_in, const int* in_sizes, int n_in,
                              void* d_out, int out_size) {
    const float* x    = (const float*)d_in[0];
    const int*   nodes= (const int*)d_in[1];
    const int*   nbr1 = (const int*)d_in[2];
    const int*   nbr2 = (const int*)d_in[3];
    const float* Ws0  = (const float*)d_in[4];
    const float* Wn0  = (const float*)d_in[5];
    const float* b0   = (const float*)d_in[6];
    const float* Ws1  = (const float*)d_in[7];
    const float* Wn1  = (const float*)d_in[8];
    const float* b1   = (const float*)d_in[9];
    const float* dl   = (const float*)d_in[10];
    const float* dw   = (const float*)d_in[11];
    const float* pw   = (const float*)d_in[12];
    const float* tb   = (const float*)d_in[13];
    float* out = (float*)d_out;

    static bool attr_done = false;
    if (!attr_done) {
        cudaFuncSetAttribute(gemm0_fused_kernel,
                             cudaFuncAttributeMaxDynamicSharedMemorySize, SMEM_SZ);
        attr_done = true;
    }

    zero_kernel<<<1, 1>>>();
    prep_kernel<<<1, 256>>>(dl, dw, pw, Ws0, Wn0, Ws1, Wn1);
    gemm0_fused_kernel<<<M0 / 128, 256, SMEM_SZ>>>(x, nodes, nbr1, nbr2, b0);
    fixup_kernel<<<256, 256>>>(x, nodes, nbr1, nbr2, Ws0, Wn0, b0);
    buildA1_kernel<<<M1, 128>>>();
    gemm1_kernel<<<M1 / 128, 256>>>(b1);
    final_kernel<<<B_, 64>>>(tb, out);
}